// round 11
// baseline (speedup 1.0000x reference)
#include <cuda_runtime.h>
#include <cuda_fp16.h>

#define NN 100000
#define EE 5000000
#define TOT (NN * 16)
#define NB_SCAN 98   // ceil(NN/1024)

// ---------------- scratch (device globals; no allocations allowed) ----------
__device__ __align__(128) float    g_s[TOT];      // layer-3 pre-BN (fp32)
__device__ __align__(128) __half2  g_hA[NN * 8];  // layer-1 pre-BN h (fp16 pairs)
__device__ __align__(128) __half2  g_hB[NN * 8];  // layer-2 pre-BN h
__device__ __align__(128) int      g_perm[EE];    // CSR: src per edge slot
__device__ __align__(128) unsigned g_cnt[NN];
__device__ __align__(128) unsigned g_off[NN];     // block-local exclusive scan
__device__ __align__(128) unsigned g_row[NN + 1];
__device__ __align__(128) unsigned g_cur[NN];
__device__ unsigned g_bsum[128];
__device__ float g_psum[1024];                    // 64 buckets x 16 features
__device__ float g_psq[1024];
__device__ float g_scale[16];
__device__ float g_shift[16];
__device__ unsigned g_tick = 0;

// ---------------- init: zero counts + stat buckets + ticket ------------------
__global__ void k_zero() {
    int i = blockIdx.x * blockDim.x + threadIdx.x;
    if (i < NN) g_cnt[i] = 0u;
    if (i < 1024) { g_psum[i] = 0.f; g_psq[i] = 0.f; }
    if (i == 0) g_tick = 0u;
}

// ---------------- CSR build --------------------------------------------------
__global__ void k_hist(const int* __restrict__ ei) {
    int e = blockIdx.x * blockDim.x + threadIdx.x;
    if (e < EE) atomicAdd(&g_cnt[__ldg(ei + EE + e)], 1u);  // no return -> REDG
}

// block-level exclusive scan of g_cnt (1024/block) + block totals
__global__ void k_scan1() {
    __shared__ unsigned wt[32];
    int t = threadIdx.x;
    int i = blockIdx.x * 1024 + t;
    unsigned v = (i < NN) ? g_cnt[i] : 0u;
    unsigned x = v;
#pragma unroll
    for (int d = 1; d < 32; d <<= 1) {
        unsigned n = __shfl_up_sync(0xffffffffu, x, d);
        if ((t & 31) >= d) x += n;
    }
    if ((t & 31) == 31) wt[t >> 5] = x;
    __syncthreads();
    if (t < 32) {
        unsigned w = wt[t];
        unsigned y = w;
#pragma unroll
        for (int d = 1; d < 32; d <<= 1) {
            unsigned n = __shfl_up_sync(0xffffffffu, y, d);
            if (t >= d) y += n;
        }
        wt[t] = y - w;
        if (t == 31) g_bsum[blockIdx.x] = y;
    }
    __syncthreads();
    if (i < NN) g_off[i] = x - v + wt[t >> 5];
}

// row starts + cursors; each block reduces its own prefix of the 98 block sums
__global__ void k_row() {
    __shared__ unsigned sws[4];
    __shared__ unsigned sbase;
    int t = threadIdx.x;
    int kb = blockIdx.x >> 2;   // which 1024-scan-tile (<= 97)
    unsigned v = (t < 128 && t < kb) ? __ldg(&g_bsum[t]) : 0u;
    if (t < 128) {
#pragma unroll
        for (int d = 16; d; d >>= 1) v += __shfl_xor_sync(0xffffffffu, v, d);
        if ((t & 31) == 0) sws[t >> 5] = v;
    }
    __syncthreads();
    if (t == 0) sbase = sws[0] + sws[1] + sws[2] + sws[3];
    __syncthreads();
    int i = blockIdx.x * 256 + t;
    if (i < NN) {
        unsigned r = g_off[i] + sbase;
        g_row[i] = r;
        g_cur[i] = r;
    }
    if (blockIdx.x == 0 && t == 0) g_row[NN] = EE;
}

__global__ void k_place(const int* __restrict__ ei) {
    int e = blockIdx.x * blockDim.x + threadIdx.x;
    if (e < EE) {
        int dst = __ldg(ei + EE + e);
        unsigned p = atomicAdd(&g_cur[dst], 1u);
        g_perm[p] = __ldg(ei + e);
    }
}

// ---------------- last-block BN finalize (ticket pattern) --------------------
__device__ __forceinline__ void tail_finalize(int t, const float* __restrict__ gam,
                                              const float* __restrict__ bet) {
    __shared__ int sdone;
    if (t == 0) {
        __threadfence();
        sdone = (atomicAdd(&g_tick, 1u) == gridDim.x - 1);
    }
    __syncthreads();
    if (sdone) {
        if (t < 16) {
            float s = 0.f, q = 0.f;
#pragma unroll
            for (int b = 0; b < 64; b++) {
                s += __ldcg(&g_psum[b * 16 + t]);
                q += __ldcg(&g_psq[b * 16 + t]);
            }
            float mean = s * (1.0f / NN);
            float var  = q * (1.0f / NN) - mean * mean;
            float sc = gam[t] * rsqrtf(var + 1e-5f);
            g_scale[t] = sc;
            g_shift[t] = bet[t] - mean * sc;
        }
        __syncthreads();  // reads done before re-zero
        for (int i = t; i < 1024; i += 256) { g_psum[i] = 0.f; g_psq[i] = 0.f; }
        if (t == 0) g_tick = 0u;
    }
}

// ---------------- layer 1: x(fp32,8) -> g_hA (fp16 pairs) + stats ------------
__global__ void __launch_bounds__(256) k_node1(
        const float* __restrict__ x, const float* __restrict__ epsp,
        const float* __restrict__ w1, const float* __restrict__ b1,
        const float* __restrict__ w2, const float* __restrict__ b2,
        const float* __restrict__ rw, const float* __restrict__ rb,
        const float* __restrict__ gam, const float* __restrict__ bet) {
    __shared__ float sw1[128], srw[128], sw2[256];
    __shared__ float sb1[16], sb2[16], srb[16];
    __shared__ float ps[16], pq[16];
    __shared__ float seps;
    int t = threadIdx.x;
    for (int i = t; i < 128; i += 256) { sw1[i] = w1[i]; srw[i] = rw[i]; }
    sw2[t] = w2[t];
    if (t < 16) { sb1[t] = b1[t]; sb2[t] = b2[t]; srb[t] = rb[t]; ps[t] = 0.f; pq[t] = 0.f; }
    if (t == 0) seps = 1.0f + *epsp;
    __syncthreads();

    int lane = t & 31;
    int node = blockIdx.x * 8 + (t >> 5);
    int f = lane & 7;
    int grp = lane >> 3;
    unsigned row = g_row[node], end = g_row[node + 1];

    float acc = 0.f;
    for (unsigned j = row + grp; j < end; j += 4) {
        int src = __ldg(g_perm + j);
        acc += __ldg(x + (size_t)src * 8 + f);
    }
    acc += __shfl_xor_sync(0xffffffffu, acc, 16);
    acc += __shfl_xor_sync(0xffffffffu, acc, 8);

    float xval = __ldg(x + (size_t)node * 8 + f);   // lane i<8 holds feature i
    float tv = seps * xval + acc;

    int o = lane & 15;
    float a = sb1[o];
#pragma unroll
    for (int i = 0; i < 8; i++)
        a = fmaf(__shfl_sync(0xffffffffu, tv, i), sw1[i * 16 + o], a);
    float h1 = (a > 0.f) ? a : 0.01f * a;           // leaky relu

    float a2 = sb2[o];
#pragma unroll
    for (int i = 0; i < 16; i++)
        a2 = fmaf(__shfl_sync(0xffffffffu, h1, i), sw2[i * 16 + o], a2);
    float r = srb[o];
#pragma unroll
    for (int i = 0; i < 8; i++)
        r = fmaf(__shfl_sync(0xffffffffu, xval, i), srw[i * 16 + o], r);
    float s = a2 + r;                                // lanes 0-15 valid

    float shi = __shfl_down_sync(0xffffffffu, s, 1);
    if (lane < 16 && !(lane & 1))
        g_hA[(size_t)node * 8 + (lane >> 1)] = __floats2half2_rn(s, shi);

    if (lane < 16) { atomicAdd(&ps[lane], s); atomicAdd(&pq[lane], s * s); }
    __syncthreads();
    if (t < 16) {
        int bkt = (blockIdx.x & 63) * 16 + t;
        atomicAdd(&g_psum[bkt], ps[t]);
        atomicAdd(&g_psq[bkt], pq[t]);
    }
    tail_finalize(t, gam, bet);
}

// ---------------- layers 2/3: gather fp16 pairs, fold BN of prev layer -------
// FROM_A: input buffer; OUT16: write half2 to other buffer, else fp32 g_s
template <bool FROM_A, bool OUT16>
__global__ void __launch_bounds__(256) k_node16(
        const float* __restrict__ epsp,
        const float* __restrict__ w1, const float* __restrict__ b1,
        const float* __restrict__ w2, const float* __restrict__ b2,
        const float* __restrict__ rw, const float* __restrict__ rb,
        const float* __restrict__ gam, const float* __restrict__ bet) {
    __shared__ float sw1[256], srw[256], sw2[256];
    __shared__ float sb1[16], sb2[16], srb[16];
    __shared__ float ssc[16], ssh[16];
    __shared__ float ps[16], pq[16];
    __shared__ float seps;
    int t = threadIdx.x;
    sw1[t] = w1[t]; srw[t] = rw[t]; sw2[t] = w2[t];
    if (t < 16) {
        sb1[t] = b1[t]; sb2[t] = b2[t]; srb[t] = rb[t];
        ssc[t] = g_scale[t]; ssh[t] = g_shift[t];
        ps[t] = 0.f; pq[t] = 0.f;
    }
    if (t == 0) seps = 1.0f + *epsp;
    __syncthreads();

    const __half2* __restrict__ hin = FROM_A ? g_hA : g_hB;
    int lane = t & 31;
    int node = blockIdx.x * 8 + (t >> 5);
    int f2 = lane & 7;                    // feature pair (2*f2, 2*f2+1)
    int grp = lane >> 3;
    unsigned row = g_row[node], end = g_row[node + 1];

    float ax = 0.f, ay = 0.f;             // raw (pre-BN) neighbor sums
    for (unsigned j = row + grp; j < end; j += 4) {
        int src = __ldg(g_perm + j);
        float2 fv = __half22float2(__ldg(&hin[(size_t)src * 8 + f2]));
        ax += fv.x; ay += fv.y;
    }
    ax += __shfl_xor_sync(0xffffffffu, ax, 16);
    ay += __shfl_xor_sync(0xffffffffu, ay, 16);
    ax += __shfl_xor_sync(0xffffffffu, ax, 8);
    ay += __shfl_xor_sync(0xffffffffu, ay, 8);

    float2 xp = __half22float2(__ldg(&hin[(size_t)node * 8 + f2]));
    float deg = (float)(end - row);
    float sc0 = ssc[2 * f2], sc1 = ssc[2 * f2 + 1];
    float sh0 = ssh[2 * f2], sh1 = ssh[2 * f2 + 1];
    // normalized: h = sc*raw + sh; tv = seps*h_self + sum(h_nbr)
    float tvx = sc0 * fmaf(seps, xp.x, ax) + (seps + deg) * sh0;
    float tvy = sc1 * fmaf(seps, xp.y, ay) + (seps + deg) * sh1;
    float xnx = fmaf(sc0, xp.x, sh0);
    float xny = fmaf(sc1, xp.y, sh1);

    int o = lane & 15;
    float a = sb1[o];
#pragma unroll
    for (int i = 0; i < 16; i++) {
        float tvi = __shfl_sync(0xffffffffu, (i & 1) ? tvy : tvx, i >> 1);
        a = fmaf(tvi, sw1[i * 16 + o], a);
    }
    float h1 = fmaxf(a, 0.f);             // relu

    float a2 = sb2[o];
#pragma unroll
    for (int i = 0; i < 16; i++)
        a2 = fmaf(__shfl_sync(0xffffffffu, h1, i), sw2[i * 16 + o], a2);
    float r = srb[o];
#pragma unroll
    for (int i = 0; i < 16; i++) {
        float xni = __shfl_sync(0xffffffffu, (i & 1) ? xny : xnx, i >> 1);
        r = fmaf(xni, srw[i * 16 + o], r);
    }
    float s = a2 + r;                     // lanes 0-15 valid

    if (OUT16) {
        float shi = __shfl_down_sync(0xffffffffu, s, 1);
        if (lane < 16 && !(lane & 1)) {
            __half2* hout = FROM_A ? g_hB : g_hA;
            hout[(size_t)node * 8 + (lane >> 1)] = __floats2half2_rn(s, shi);
        }
    } else {
        if (lane < 16) g_s[(size_t)node * 16 + lane] = s;
    }

    if (lane < 16) { atomicAdd(&ps[lane], s); atomicAdd(&pq[lane], s * s); }
    __syncthreads();
    if (t < 16) {
        int bkt = (blockIdx.x & 63) * 16 + t;
        atomicAdd(&g_psum[bkt], ps[t]);
        atomicAdd(&g_psq[bkt], pq[t]);
    }
    tail_finalize(t, gam, bet);
}

// ---------------- final BN apply ---------------------------------------------
__global__ void k_apply(float* __restrict__ out) {
    int i = blockIdx.x * blockDim.x + threadIdx.x;  // over TOT/4 float4s
    if (i < TOT / 4) {
        float4 v  = reinterpret_cast<const float4*>(g_s)[i];
        float4 sc = reinterpret_cast<const float4*>(g_scale)[i & 3];
        float4 sh = reinterpret_cast<const float4*>(g_shift)[i & 3];
        v.x = fmaf(v.x, sc.x, sh.x);
        v.y = fmaf(v.y, sc.y, sh.y);
        v.z = fmaf(v.z, sc.z, sh.z);
        v.w = fmaf(v.w, sc.w, sh.w);
        reinterpret_cast<float4*>(out)[i] = v;
    }
}

// ---------------- launch ------------------------------------------------------
extern "C" void kernel_launch(void* const* d_in, const int* in_sizes, int n_in,
                              void* d_out, int out_size) {
    const float* x   = (const float*)d_in[0];
    const int*   ei  = (const int*)d_in[1];
    const float *eps1 = (const float*)d_in[2],  *w11 = (const float*)d_in[3],
                *b11  = (const float*)d_in[4],  *w12 = (const float*)d_in[5],
                *b12  = (const float*)d_in[6],  *rw1 = (const float*)d_in[7],
                *rb1  = (const float*)d_in[8],  *g1  = (const float*)d_in[9],
                *be1  = (const float*)d_in[10];
    const float *eps2 = (const float*)d_in[11], *w21 = (const float*)d_in[12],
                *b21  = (const float*)d_in[13], *w22 = (const float*)d_in[14],
                *b22  = (const float*)d_in[15], *rw2 = (const float*)d_in[16],
                *rb2  = (const float*)d_in[17], *g2  = (const float*)d_in[18],
                *be2  = (const float*)d_in[19];
    const float *eps3 = (const float*)d_in[20], *w31 = (const float*)d_in[21],
                *b31  = (const float*)d_in[22], *w32 = (const float*)d_in[23],
                *b32  = (const float*)d_in[24], *rw3 = (const float*)d_in[25],
                *rb3  = (const float*)d_in[26], *g3  = (const float*)d_in[27],
                *be3  = (const float*)d_in[28];
    float* out = (float*)d_out;

    const int TB = 256;
    dim3 ge((EE + TB - 1) / TB);
    dim3 gn((NN + TB - 1) / TB);     // 391
    dim3 ga((TOT / 4 + TB - 1) / TB);
    dim3 gw(NN / 8);                 // 12500, warp per node

    // ---- CSR build (per call; deterministic) ----
    k_zero<<<gn, TB>>>();
    k_hist<<<ge, TB>>>(ei);
    k_scan1<<<NB_SCAN, 1024>>>();
    k_row<<<gn, TB>>>();
    k_place<<<ge, TB>>>(ei);

    // ---- 3 fused GIN blocks (BN folded into the following gather) ----
    k_node1<<<gw, TB>>>(x, eps1, w11, b11, w12, b12, rw1, rb1, g1, be1);
    k_node16<true,  true ><<<gw, TB>>>(eps2, w21, b21, w22, b22, rw2, rb2, g2, be2);
    k_node16<false, false><<<gw, TB>>>(eps3, w31, b31, w32, b32, rw3, rb3, g3, be3);
    k_apply<<<ga, TB>>>(out);
}